// round 6
// baseline (speedup 1.0000x reference)
#include <cuda_runtime.h>
#include <cstdint>
#include <cstddef>

// Problem dims
#define M_DIM 8192
#define K_DIM 4096
#define N_DIM 11008

// GEMM tiling
#define BM 128
#define BN 128
#define BK 64          // int8 bytes of K per stage
#define STAGES 4
#define NITER (K_DIM / BK)      // 64
#define ROWB 80                 // padded smem row: 64B data + 16B pad (bank-rotating)
#define TILE_BYTES (BM * ROWB)  // 10240
#define STAGE_BYTES (3 * TILE_BYTES)        // Ahi | Alo | W = 30720
#define SMEM_BYTES (STAGES * STAGE_BYTES)   // 122880

// Scratch (device globals — no runtime allocation allowed)
__device__ char  g_xh[(size_t)M_DIM * K_DIM];   // x hi-byte plane (int8)
__device__ char  g_xl[(size_t)M_DIM * K_DIM];   // x lo-byte plane (int8)
__device__ char  g_w [(size_t)N_DIM * K_DIM];   // Wq repacked to int8
__device__ float g_xs[M_DIM];                   // per-row x scale

// ---------------- PTX helpers (portable ISA only: sm_80+) ----------------
__device__ __forceinline__ uint32_t smem_u32(const void* p) {
    uint32_t a;
    asm("{ .reg .u64 t; cvta.to.shared.u64 t, %1; cvt.u32.u64 %0, t; }"
        : "=r"(a) : "l"(p));
    return a;
}
__device__ __forceinline__ void cp16(uint32_t s, const void* g) {
    asm volatile("cp.async.cg.shared.global [%0], [%1], 16;" :: "r"(s), "l"(g) : "memory");
}
#define CP_COMMIT() asm volatile("cp.async.commit_group;" ::: "memory")
#define CP_WAIT(n)  asm volatile("cp.async.wait_group %0;" :: "n"(n) : "memory")

__device__ __forceinline__ void ldsm4(uint32_t* d, uint32_t addr) {
    asm volatile("ldmatrix.sync.aligned.m8n8.x4.shared.b16 {%0,%1,%2,%3}, [%4];"
                 : "=r"(d[0]), "=r"(d[1]), "=r"(d[2]), "=r"(d[3]) : "r"(addr));
}
// D = A(16x32 s8) * B(32x8 s8)^T + D, s32 accum
__device__ __forceinline__ void mma_s8(int* c, const uint32_t* a, uint32_t b0, uint32_t b1) {
    asm volatile(
        "mma.sync.aligned.m16n8k32.row.col.s32.s8.s8.s32 "
        "{%0,%1,%2,%3},{%4,%5,%6,%7},{%8,%9},{%0,%1,%2,%3};"
        : "+r"(c[0]), "+r"(c[1]), "+r"(c[2]), "+r"(c[3])
        : "r"(a[0]), "r"(a[1]), "r"(a[2]), "r"(a[3]), "r"(b0), "r"(b1));
}

// ---------------- prepass 1: x -> per-row 16-bit fixed point (2 int8 planes) ----------------
__global__ void quant_x_kernel(const float* __restrict__ x) {
    const int row = blockIdx.x;
    const int tid = threadIdx.x;
    const float4* xr = reinterpret_cast<const float4*>(x + (size_t)row * K_DIM) + tid * 4;

    float4 v[4];
    float mx = 0.0f;
#pragma unroll
    for (int i = 0; i < 4; ++i) {
        v[i] = xr[i];
        mx = fmaxf(mx, fmaxf(fmaxf(fabsf(v[i].x), fabsf(v[i].y)),
                             fmaxf(fabsf(v[i].z), fabsf(v[i].w))));
    }
    __shared__ float red[256];
    red[tid] = mx;
    __syncthreads();
#pragma unroll
    for (int s = 128; s > 0; s >>= 1) {
        if (tid < s) red[tid] = fmaxf(red[tid], red[tid + s]);
        __syncthreads();
    }
    const float maxv = red[0];
    const float inv  = (maxv > 0.0f) ? (32512.0f / maxv) : 0.0f;
    if (tid == 0) g_xs[row] = maxv * (1.0f / 32512.0f);

    const float* vf = reinterpret_cast<const float*>(v);
    uint32_t ph[4], pl[4];
#pragma unroll
    for (int g = 0; g < 4; ++g) {
        uint32_t hh = 0, ll = 0;
#pragma unroll
        for (int j = 0; j < 4; ++j) {
            int q = __float2int_rn(vf[g * 4 + j] * inv);
            q = max(-32512, min(32512, q));
            int h = (q + 128) >> 8;          // arithmetic shift: h in [-127,127]
            int l = q - (h << 8);            // l in [-128,127]
            hh |= (uint32_t)(h & 0xFF) << (8 * j);
            ll |= (uint32_t)(l & 0xFF) << (8 * j);
        }
        ph[g] = hh; pl[g] = ll;
    }
    const size_t o = ((size_t)row * K_DIM + (size_t)tid * 16) / 16;
    reinterpret_cast<uint4*>(g_xh)[o] = make_uint4(ph[0], ph[1], ph[2], ph[3]);
    reinterpret_cast<uint4*>(g_xl)[o] = make_uint4(pl[0], pl[1], pl[2], pl[3]);
}

// ---------------- prepass 2: Wq int32 -> int8 ----------------
__global__ void repack_w_kernel(const int4* __restrict__ wq, int n4) {
    const int i = blockIdx.x * blockDim.x + threadIdx.x;
    if (i >= n4) return;
    int4 a = wq[i];
    uint32_t p = (uint32_t)(a.x & 0xFF) | ((uint32_t)(a.y & 0xFF) << 8) |
                 ((uint32_t)(a.z & 0xFF) << 16) | ((uint32_t)(a.w & 0xFF) << 24);
    reinterpret_cast<uint32_t*>(g_w)[i] = p;
}

// ---------------- GEMM ----------------
__device__ __forceinline__ void load_stage(uint32_t sbase,
                                           const char* __restrict__ Ah,
                                           const char* __restrict__ Al,
                                           const char* __restrict__ Bw,
                                           int kc, int tid) {
    const int kb = kc * BK;
    // each tile: 128 rows x 4 chunks of 16B = 512 chunks; 2 per thread per tile
#pragma unroll
    for (int i = 0; i < 2; ++i) {
        const int q = i * 256 + tid;
        const int r = q >> 2, c = q & 3;
        const uint32_t so = (uint32_t)r * ROWB + c * 16;
        const size_t go = (size_t)r * K_DIM + kb + c * 16;
        cp16(sbase + so,                  Ah + go);
        cp16(sbase + TILE_BYTES + so,     Al + go);
        cp16(sbase + 2 * TILE_BYTES + so, Bw + go);
    }
}

__device__ __forceinline__ void tile_compute(uint32_t st, int l, int wm, int wn,
                                             int ch[4][4][4], int cl[4][4][4]) {
    const uint32_t aH = st;
    const uint32_t aL = st + TILE_BYTES;
    const uint32_t bB = st + 2 * TILE_BYTES;
    const int r = l & 7, mi = l >> 3;
    // ldmatrix.x4 lane->matrix mapping: lanes [8k..8k+7] give matrix k row addresses
    const uint32_t aoff = (uint32_t)(wm + ((mi & 1) << 3) + r) * ROWB + ((mi >> 1) << 4);
    const uint32_t boff = (uint32_t)(wn + ((mi >> 1) << 3) + r) * ROWB + ((mi & 1) << 4);

#pragma unroll
    for (int ks = 0; ks < 2; ++ks) {
        const uint32_t ko = ks * 32;
        uint32_t bt[2][4];
        ldsm4(bt[0], bB + boff + ko);
        ldsm4(bt[1], bB + boff + 16 * ROWB + ko);
        uint32_t ah[4][4], al[4][4];
#pragma unroll
        for (int i = 0; i < 4; ++i) ldsm4(ah[i], aH + aoff + i * 16 * ROWB + ko);
#pragma unroll
        for (int i = 0; i < 4; ++i) ldsm4(al[i], aL + aoff + i * 16 * ROWB + ko);
#pragma unroll
        for (int i = 0; i < 4; ++i) {
#pragma unroll
            for (int j = 0; j < 4; ++j) {
                const uint32_t b0 = bt[j >> 1][(j & 1) * 2];
                const uint32_t b1 = bt[j >> 1][(j & 1) * 2 + 1];
                mma_s8(ch[i][j], ah[i], b0, b1);
                mma_s8(cl[i][j], al[i], b0, b1);
            }
        }
    }
}

__global__ void __launch_bounds__(256, 1)
gemm_kernel(const float* __restrict__ scale, const float* __restrict__ bias,
            float* __restrict__ out) {
    extern __shared__ char smem[];
    const uint32_t sb = smem_u32(smem);
    const int tid = threadIdx.x;
    const int wid = tid >> 5;
    const int l = tid & 31;

    const int mt = blockIdx.x;   // fastest -> consecutive CTAs share W tile; A stays L2-resident
    const int nt = blockIdx.y;
    const size_t mBase = (size_t)mt * BM;
    const size_t nBase = (size_t)nt * BN;

    const char* Ah = g_xh + mBase * K_DIM;
    const char* Al = g_xl + mBase * K_DIM;
    const char* Bw = g_w + nBase * K_DIM;

    const int wm = (wid & 1) * 64;
    const int wn = (wid >> 1) * 32;

    int ch[4][4][4], cl[4][4][4];
#pragma unroll
    for (int i = 0; i < 4; ++i)
#pragma unroll
        for (int j = 0; j < 4; ++j)
#pragma unroll
            for (int k = 0; k < 4; ++k) { ch[i][j][k] = 0; cl[i][j][k] = 0; }

    // prologue: stages 0..2
#pragma unroll
    for (int s = 0; s < STAGES - 1; ++s) {
        load_stage(sb + s * STAGE_BYTES, Ah, Al, Bw, s, tid);
        CP_COMMIT();
    }

    for (int it = 0; it < NITER; ++it) {
        CP_WAIT(STAGES - 2);
        __syncthreads();
        if (it + STAGES - 1 < NITER)
            load_stage(sb + ((it + STAGES - 1) & (STAGES - 1)) * STAGE_BYTES,
                       Ah, Al, Bw, it + STAGES - 1, tid);
        CP_COMMIT();   // always commit so wait-count stays aligned in the tail
        tile_compute(sb + (it & (STAGES - 1)) * STAGE_BYTES, l, wm, wn, ch, cl);
    }

    // ---------------- epilogue: dequant + bias + exact GELU ----------------
    const int gid = l >> 2, tig = l & 3;

    float sx[8];
#pragma unroll
    for (int i = 0; i < 4; ++i) {
        sx[2 * i]     = g_xs[mBase + wm + 16 * i + gid];
        sx[2 * i + 1] = g_xs[mBase + wm + 16 * i + gid + 8];
    }
    float wv[8], bv[8];
#pragma unroll
    for (int j = 0; j < 4; ++j) {
        const size_t n0 = nBase + wn + 8 * j + 2 * tig;
        wv[2 * j] = scale[n0]; wv[2 * j + 1] = scale[n0 + 1];
        bv[2 * j] = bias[n0];  bv[2 * j + 1] = bias[n0 + 1];
    }

#pragma unroll
    for (int i = 0; i < 4; ++i) {
#pragma unroll
        for (int j = 0; j < 4; ++j) {
            const size_t n0 = nBase + wn + 8 * j + 2 * tig;
#pragma unroll
            for (int h = 0; h < 2; ++h) {
                const size_t m = mBase + wm + 16 * i + gid + 8 * h;
                const float sm = sx[2 * i + h];
                float v0 = fmaf(256.0f, (float)ch[i][j][2 * h],     (float)cl[i][j][2 * h]);
                float v1 = fmaf(256.0f, (float)ch[i][j][2 * h + 1], (float)cl[i][j][2 * h + 1]);
                float y0 = fmaf(v0, sm * wv[2 * j],     bv[2 * j]);
                float y1 = fmaf(v1, sm * wv[2 * j + 1], bv[2 * j + 1]);
                float g0 = 0.5f * y0 * (1.0f + erff(y0 * 0.70710678118654752f));
                float g1 = 0.5f * y1 * (1.0f + erff(y1 * 0.70710678118654752f));
                float2 vv; vv.x = g0; vv.y = g1;
                __stcg(reinterpret_cast<float2*>(out + m * N_DIM + n0), vv);  // bypass L2: keep A/W resident
            }
        }
    }
}

// ---------------- launch ----------------
extern "C" void kernel_launch(void* const* d_in, const int* in_sizes, int n_in,
                              void* d_out, int out_size) {
    const float* x     = (const float*)d_in[0];
    const int*   Wq    = (const int*)d_in[1];
    const float* scale = (const float*)d_in[2];
    const float* bias  = (const float*)d_in[3];
    float* out = (float*)d_out;
    (void)in_sizes; (void)n_in; (void)out_size;

    // x -> per-row fixed-point hi/lo int8 planes
    quant_x_kernel<<<M_DIM, 256>>>(x);
    // Wq int32 -> int8
    {
        const int n4 = (N_DIM * K_DIM) / 4;   // 11272192
        repack_w_kernel<<<(n4 + 255) / 256, 256>>>((const int4*)Wq, n4);
    }
    // GEMM + fused epilogue
    cudaFuncSetAttribute(gemm_kernel, cudaFuncAttributeMaxDynamicSharedMemorySize,
                         SMEM_BYTES);
    dim3 grid(M_DIM / BM, N_DIM / BN);        // (64, 86), mt fastest
    gemm_kernel<<<grid, 256, SMEM_BYTES>>>(scale, bias, out);
}

// round 7
// speedup vs baseline: 1.0454x; 1.0454x over previous
#include <cuda_runtime.h>
#include <cstdint>
#include <cstddef>

// Problem dims
#define M_DIM 8192
#define K_DIM 4096
#define N_DIM 11008

// GEMM tiling
#define BM 128
#define BN 128
#define BK 64          // int8 bytes of K per stage
#define STAGES 4
#define NITER (K_DIM / BK)      // 64
#define THREADS 512             // 16 warps, 4x4 warp grid, 32x32 warp tile
#define ROWB 80                 // padded smem row: 64B data + 16B pad (bank-rotating)
#define TILE_BYTES (BM * ROWB)  // 10240
#define STAGE_BYTES (3 * TILE_BYTES)        // Ahi | Alo | W = 30720
#define SMEM_BYTES (STAGES * STAGE_BYTES)   // 122880

// Scratch (device globals — no runtime allocation allowed)
__device__ char  g_xh[(size_t)M_DIM * K_DIM];   // x hi-byte plane (int8)
__device__ char  g_xl[(size_t)M_DIM * K_DIM];   // x lo-byte plane (int8)
__device__ char  g_w [(size_t)N_DIM * K_DIM];   // Wq repacked to int8
__device__ float g_xs[M_DIM];                   // per-row x scale

// ---------------- PTX helpers (portable ISA only: sm_80+) ----------------
__device__ __forceinline__ uint32_t smem_u32(const void* p) {
    uint32_t a;
    asm("{ .reg .u64 t; cvta.to.shared.u64 t, %1; cvt.u32.u64 %0, t; }"
        : "=r"(a) : "l"(p));
    return a;
}
__device__ __forceinline__ void cp16(uint32_t s, const void* g) {
    asm volatile("cp.async.cg.shared.global [%0], [%1], 16;" :: "r"(s), "l"(g) : "memory");
}
#define CP_COMMIT() asm volatile("cp.async.commit_group;" ::: "memory")
#define CP_WAIT(n)  asm volatile("cp.async.wait_group %0;" :: "n"(n) : "memory")

__device__ __forceinline__ void ldsm4(uint32_t* d, uint32_t addr) {
    asm volatile("ldmatrix.sync.aligned.m8n8.x4.shared.b16 {%0,%1,%2,%3}, [%4];"
                 : "=r"(d[0]), "=r"(d[1]), "=r"(d[2]), "=r"(d[3]) : "r"(addr));
}
// D = A(16x32 s8) * B(32x8 s8)^T + D, s32 accum
__device__ __forceinline__ void mma_s8(int* c, const uint32_t* a, uint32_t b0, uint32_t b1) {
    asm volatile(
        "mma.sync.aligned.m16n8k32.row.col.s32.s8.s8.s32 "
        "{%0,%1,%2,%3},{%4,%5,%6,%7},{%8,%9},{%0,%1,%2,%3};"
        : "+r"(c[0]), "+r"(c[1]), "+r"(c[2]), "+r"(c[3])
        : "r"(a[0]), "r"(a[1]), "r"(a[2]), "r"(a[3]), "r"(b0), "r"(b1));
}

// ---------------- prepass 1: x -> per-row 16-bit fixed point (2 int8 planes) ----------------
__global__ void quant_x_kernel(const float* __restrict__ x) {
    const int row = blockIdx.x;
    const int tid = threadIdx.x;
    const float4* xr = reinterpret_cast<const float4*>(x + (size_t)row * K_DIM) + tid * 4;

    float4 v[4];
    float mx = 0.0f;
#pragma unroll
    for (int i = 0; i < 4; ++i) {
        v[i] = xr[i];
        mx = fmaxf(mx, fmaxf(fmaxf(fabsf(v[i].x), fabsf(v[i].y)),
                             fmaxf(fabsf(v[i].z), fabsf(v[i].w))));
    }
    __shared__ float red[256];
    red[tid] = mx;
    __syncthreads();
#pragma unroll
    for (int s = 128; s > 0; s >>= 1) {
        if (tid < s) red[tid] = fmaxf(red[tid], red[tid + s]);
        __syncthreads();
    }
    const float maxv = red[0];
    const float inv  = (maxv > 0.0f) ? (32512.0f / maxv) : 0.0f;
    if (tid == 0) g_xs[row] = maxv * (1.0f / 32512.0f);

    const float* vf = reinterpret_cast<const float*>(v);
    uint32_t ph[4], pl[4];
#pragma unroll
    for (int g = 0; g < 4; ++g) {
        uint32_t hh = 0, ll = 0;
#pragma unroll
        for (int j = 0; j < 4; ++j) {
            int q = __float2int_rn(vf[g * 4 + j] * inv);
            q = max(-32512, min(32512, q));
            int h = (q + 128) >> 8;          // arithmetic shift: h in [-127,127]
            int l = q - (h << 8);            // l in [-128,127]
            hh |= (uint32_t)(h & 0xFF) << (8 * j);
            ll |= (uint32_t)(l & 0xFF) << (8 * j);
        }
        ph[g] = hh; pl[g] = ll;
    }
    const size_t o = ((size_t)row * K_DIM + (size_t)tid * 16) / 16;
    reinterpret_cast<uint4*>(g_xh)[o] = make_uint4(ph[0], ph[1], ph[2], ph[3]);
    reinterpret_cast<uint4*>(g_xl)[o] = make_uint4(pl[0], pl[1], pl[2], pl[3]);
}

// ---------------- prepass 2: Wq int32 -> int8 ----------------
__global__ void repack_w_kernel(const int4* __restrict__ wq, int n4) {
    const int i = blockIdx.x * blockDim.x + threadIdx.x;
    if (i >= n4) return;
    int4 a = wq[i];
    uint32_t p = (uint32_t)(a.x & 0xFF) | ((uint32_t)(a.y & 0xFF) << 8) |
                 ((uint32_t)(a.z & 0xFF) << 16) | ((uint32_t)(a.w & 0xFF) << 24);
    reinterpret_cast<uint32_t*>(g_w)[i] = p;
}

// ---------------- GEMM ----------------
__device__ __forceinline__ void load_stage(uint32_t sbase,
                                           const char* __restrict__ Ah,
                                           const char* __restrict__ Al,
                                           const char* __restrict__ Bw,
                                           int kc, int tid) {
    const int kb = kc * BK;
    // each tile: 128 rows x 4 chunks of 16B = 512 chunks; 1 per thread per tile
    const int r = tid >> 2, c = tid & 3;
    const uint32_t so = (uint32_t)r * ROWB + c * 16;
    const size_t go = (size_t)r * K_DIM + kb + c * 16;
    cp16(sbase + so,                  Ah + go);
    cp16(sbase + TILE_BYTES + so,     Al + go);
    cp16(sbase + 2 * TILE_BYTES + so, Bw + go);
}

__device__ __forceinline__ void tile_compute(uint32_t st, int l, int wm, int wn,
                                             int ch[2][4][4], int cl[2][4][4]) {
    const uint32_t aH = st;
    const uint32_t aL = st + TILE_BYTES;
    const uint32_t bB = st + 2 * TILE_BYTES;
    const int r = l & 7, mi4 = l >> 3;
    // ldmatrix.x4 lane->matrix mapping: lanes [8k..8k+7] give matrix k row addresses
    const uint32_t aoff = (uint32_t)(wm + ((mi4 & 1) << 3) + r) * ROWB + ((mi4 >> 1) << 4);
    const uint32_t boff = (uint32_t)(wn + ((mi4 >> 1) << 3) + r) * ROWB + ((mi4 & 1) << 4);

#pragma unroll
    for (int ks = 0; ks < 2; ++ks) {
        const uint32_t ko = ks * 32;
        uint32_t bt[2][4];
        ldsm4(bt[0], bB + boff + ko);
        ldsm4(bt[1], bB + boff + 16 * ROWB + ko);
        uint32_t ah[2][4], al[2][4];
#pragma unroll
        for (int i = 0; i < 2; ++i) ldsm4(ah[i], aH + aoff + i * 16 * ROWB + ko);
#pragma unroll
        for (int i = 0; i < 2; ++i) ldsm4(al[i], aL + aoff + i * 16 * ROWB + ko);
#pragma unroll
        for (int i = 0; i < 2; ++i) {
#pragma unroll
            for (int j = 0; j < 4; ++j) {
                const uint32_t b0 = bt[j >> 1][(j & 1) * 2];
                const uint32_t b1 = bt[j >> 1][(j & 1) * 2 + 1];
                mma_s8(ch[i][j], ah[i], b0, b1);
                mma_s8(cl[i][j], al[i], b0, b1);
            }
        }
    }
}

__global__ void __launch_bounds__(THREADS, 1)
gemm_kernel(const float* __restrict__ scale, const float* __restrict__ bias,
            float* __restrict__ out) {
    extern __shared__ char smem[];
    const uint32_t sb = smem_u32(smem);
    const int tid = threadIdx.x;
    const int wid = tid >> 5;        // 0..15
    const int l = tid & 31;

    const int mt = blockIdx.x;   // fastest -> A planes stay L2-resident across nt sweeps
    const int nt = blockIdx.y;
    const size_t mBase = (size_t)mt * BM;
    const size_t nBase = (size_t)nt * BN;

    const char* Ah = g_xh + mBase * K_DIM;
    const char* Al = g_xl + mBase * K_DIM;
    const char* Bw = g_w + nBase * K_DIM;

    const int wm = (wid & 3) * 32;   // 4x4 warp grid, 32x32 warp tile
    const int wn = (wid >> 2) * 32;

    int ch[2][4][4], cl[2][4][4];    // 64 accumulator regs (no spill)
#pragma unroll
    for (int i = 0; i < 2; ++i)
#pragma unroll
        for (int j = 0; j < 4; ++j)
#pragma unroll
            for (int k = 0; k < 4; ++k) { ch[i][j][k] = 0; cl[i][j][k] = 0; }

    // prologue: stages 0..2
#pragma unroll
    for (int s = 0; s < STAGES - 1; ++s) {
        load_stage(sb + s * STAGE_BYTES, Ah, Al, Bw, s, tid);
        CP_COMMIT();
    }

    for (int it = 0; it < NITER; ++it) {
        CP_WAIT(STAGES - 2);
        __syncthreads();
        if (it + STAGES - 1 < NITER)
            load_stage(sb + ((it + STAGES - 1) & (STAGES - 1)) * STAGE_BYTES,
                       Ah, Al, Bw, it + STAGES - 1, tid);
        CP_COMMIT();   // always commit so wait-count stays aligned in the tail
        tile_compute(sb + (it & (STAGES - 1)) * STAGE_BYTES, l, wm, wn, ch, cl);
    }

    // ---------------- epilogue: dequant + bias + exact GELU ----------------
    const int gid = l >> 2, tig = l & 3;

    float sx[2][2];
#pragma unroll
    for (int i = 0; i < 2; ++i) {
        sx[i][0] = g_xs[mBase + wm + 16 * i + gid];
        sx[i][1] = g_xs[mBase + wm + 16 * i + gid + 8];
    }
    float wv[8], bv[8];
#pragma unroll
    for (int j = 0; j < 4; ++j) {
        const size_t n0 = nBase + wn + 8 * j + 2 * tig;
        wv[2 * j] = scale[n0]; wv[2 * j + 1] = scale[n0 + 1];
        bv[2 * j] = bias[n0];  bv[2 * j + 1] = bias[n0 + 1];
    }

#pragma unroll
    for (int i = 0; i < 2; ++i) {
#pragma unroll
        for (int j = 0; j < 4; ++j) {
            const size_t n0 = nBase + wn + 8 * j + 2 * tig;
#pragma unroll
            for (int h = 0; h < 2; ++h) {
                const size_t m = mBase + wm + 16 * i + gid + 8 * h;
                const float sm = sx[i][h];
                float v0 = fmaf(256.0f, (float)ch[i][j][2 * h],     (float)cl[i][j][2 * h]);
                float v1 = fmaf(256.0f, (float)ch[i][j][2 * h + 1], (float)cl[i][j][2 * h + 1]);
                float y0 = fmaf(v0, sm * wv[2 * j],     bv[2 * j]);
                float y1 = fmaf(v1, sm * wv[2 * j + 1], bv[2 * j + 1]);
                float g0 = 0.5f * y0 * (1.0f + erff(y0 * 0.70710678118654752f));
                float g1 = 0.5f * y1 * (1.0f + erff(y1 * 0.70710678118654752f));
                float2 vv; vv.x = g0; vv.y = g1;
                __stcg(reinterpret_cast<float2*>(out + m * N_DIM + n0), vv);  // bypass L2: keep A/W resident
            }
        }
    }
}

// ---------------- launch ----------------
extern "C" void kernel_launch(void* const* d_in, const int* in_sizes, int n_in,
                              void* d_out, int out_size) {
    const float* x     = (const float*)d_in[0];
    const int*   Wq    = (const int*)d_in[1];
    const float* scale = (const float*)d_in[2];
    const float* bias  = (const float*)d_in[3];
    float* out = (float*)d_out;
    (void)in_sizes; (void)n_in; (void)out_size;

    // x -> per-row fixed-point hi/lo int8 planes
    quant_x_kernel<<<M_DIM, 256>>>(x);
    // Wq int32 -> int8
    {
        const int n4 = (N_DIM * K_DIM) / 4;   // 11272192
        repack_w_kernel<<<(n4 + 255) / 256, 256>>>((const int4*)Wq, n4);
    }
    // GEMM + fused epilogue
    cudaFuncSetAttribute(gemm_kernel, cudaFuncAttributeMaxDynamicSharedMemorySize,
                         SMEM_BYTES);
    dim3 grid(M_DIM / BM, N_DIM / BN);        // (64, 86), mt fastest
    gemm_kernel<<<grid, THREADS, SMEM_BYTES>>>(scale, bias, out);
}

// round 8
// speedup vs baseline: 2.6254x; 2.5113x over previous
#include <cuda_runtime.h>
#include <cuda_bf16.h>
#include <cstdint>
#include <cstddef>

// Problem dims
#define M_DIM 8192
#define K_DIM 4096
#define N_DIM 11008

// GEMM tiling (bf16 path)
#define BM 128
#define BN 128
#define BKE 64          // K elements (bf16) per stage = 128 bytes per row
#define STAGES 3
#define NITER (K_DIM / BKE)     // 64
#define THREADS 512             // 16 warps, 4x4 warp grid, 32x32 warp tile
#define ROWB 144                // 128B data + 16B pad (bank-rotating, ldsm conflict-free)
#define TILE_BYTES (BM * ROWB)              // 18432
#define STAGE_BYTES (3 * TILE_BYTES)        // Ahi | Alo | W = 55296
#define SMEM_BYTES (STAGES * STAGE_BYTES)   // 165888

// Scratch (device globals — no runtime allocation allowed)
__device__ __nv_bfloat16 g_xh[(size_t)M_DIM * K_DIM];   // x hi plane (bf16)
__device__ __nv_bfloat16 g_xl[(size_t)M_DIM * K_DIM];   // x residual plane (bf16)
__device__ __nv_bfloat16 g_w [(size_t)N_DIM * K_DIM];   // Wq as bf16 (exact)

// ---------------- PTX helpers (portable ISA only: sm_80+) ----------------
__device__ __forceinline__ uint32_t smem_u32(const void* p) {
    uint32_t a;
    asm("{ .reg .u64 t; cvta.to.shared.u64 t, %1; cvt.u32.u64 %0, t; }"
        : "=r"(a) : "l"(p));
    return a;
}
__device__ __forceinline__ void cp16(uint32_t s, const void* g) {
    asm volatile("cp.async.cg.shared.global [%0], [%1], 16;" :: "r"(s), "l"(g) : "memory");
}
#define CP_COMMIT() asm volatile("cp.async.commit_group;" ::: "memory")
#define CP_WAIT(n)  asm volatile("cp.async.wait_group %0;" :: "n"(n) : "memory")

__device__ __forceinline__ void ldsm4(uint32_t* d, uint32_t addr) {
    asm volatile("ldmatrix.sync.aligned.m8n8.x4.shared.b16 {%0,%1,%2,%3}, [%4];"
                 : "=r"(d[0]), "=r"(d[1]), "=r"(d[2]), "=r"(d[3]) : "r"(addr));
}
// C(f32) += A(16x16 bf16) * B(16x8 bf16)^T
__device__ __forceinline__ void mma_bf16(float* c, const uint32_t* a, uint32_t b0, uint32_t b1) {
    asm volatile(
        "mma.sync.aligned.m16n8k16.row.col.f32.bf16.bf16.f32 "
        "{%0,%1,%2,%3},{%4,%5,%6,%7},{%8,%9},{%0,%1,%2,%3};"
        : "+f"(c[0]), "+f"(c[1]), "+f"(c[2]), "+f"(c[3])
        : "r"(a[0]), "r"(a[1]), "r"(a[2]), "r"(a[3]), "r"(b0), "r"(b1));
}

// ---------------- prepass 1: x -> bf16 hi + bf16 residual ----------------
__device__ __forceinline__ uint32_t pack_bf2(float a, float b) {
    __nv_bfloat162 t = __floats2bfloat162_rn(a, b);
    return *reinterpret_cast<uint32_t*>(&t);
}
__global__ void cvt_x_kernel(const float4* __restrict__ x, int n4) {
    int i = blockIdx.x * blockDim.x + threadIdx.x;
    if (i >= n4) return;
    float4 v = x[i];
    float h0 = __bfloat162float(__float2bfloat16(v.x));
    float h1 = __bfloat162float(__float2bfloat16(v.y));
    float h2 = __bfloat162float(__float2bfloat16(v.z));
    float h3 = __bfloat162float(__float2bfloat16(v.w));
    uint2 hi = make_uint2(pack_bf2(v.x, v.y), pack_bf2(v.z, v.w));
    uint2 lo = make_uint2(pack_bf2(v.x - h0, v.y - h1), pack_bf2(v.z - h2, v.w - h3));
    reinterpret_cast<uint2*>(g_xh)[i] = hi;
    reinterpret_cast<uint2*>(g_xl)[i] = lo;
}

// ---------------- prepass 2: Wq int32 -> bf16 (exact for |w|<=127) ----------------
__global__ void cvt_w_kernel(const int4* __restrict__ wq, int n4) {
    int i = blockIdx.x * blockDim.x + threadIdx.x;
    if (i >= n4) return;
    int4 q = wq[i];
    uint2 o = make_uint2(pack_bf2((float)q.x, (float)q.y), pack_bf2((float)q.z, (float)q.w));
    reinterpret_cast<uint2*>(g_w)[i] = o;
}

// ---------------- GEMM ----------------
__device__ __forceinline__ void load_stage(uint32_t sbase,
                                           const __nv_bfloat16* __restrict__ Ah,
                                           const __nv_bfloat16* __restrict__ Al,
                                           const __nv_bfloat16* __restrict__ Bw,
                                           int kc, int tid) {
    const int kb = kc * BKE;
    // per tile: 128 rows x 8 chunks of 16B = 1024 chunks; 2 per thread per tile
#pragma unroll
    for (int i = 0; i < 2; ++i) {
        const int q = i * THREADS + tid;
        const int r = q >> 3, c = q & 7;
        const uint32_t so = (uint32_t)r * ROWB + c * 16;
        const size_t ge = (size_t)r * K_DIM + kb + c * 8;   // bf16 elements
        cp16(sbase + so,                  Ah + ge);
        cp16(sbase + TILE_BYTES + so,     Al + ge);
        cp16(sbase + 2 * TILE_BYTES + so, Bw + ge);
    }
}

__device__ __forceinline__ void tile_compute(uint32_t st, int l, int wm, int wn,
                                             float c[2][4][4]) {
    const uint32_t aH = st;
    const uint32_t aL = st + TILE_BYTES;
    const uint32_t bB = st + 2 * TILE_BYTES;
    const int r = l & 7, mi = l >> 3;
    // A: mat idx bit0 = +8 rows, bit1 = k-half(+16B) -> frag order {R0..R3} for m16n8k16
    const uint32_t aoff = (uint32_t)(wm + ((mi & 1) << 3) + r) * ROWB + ((mi >> 1) << 4);
    // B: mat idx bit1 = +8 n-rows, bit0 = k-half
    const uint32_t boff = (uint32_t)(wn + ((mi >> 1) << 3) + r) * ROWB + ((mi & 1) << 4);

#pragma unroll
    for (int ks = 0; ks < 4; ++ks) {
        const uint32_t ko = ks * 32;              // 16 bf16 = 32 bytes per k-step
        uint32_t bt[2][4];
        ldsm4(bt[0], bB + boff + ko);             // n 0..15
        ldsm4(bt[1], bB + boff + 16 * ROWB + ko); // n 16..31
        uint32_t ah[2][4], al[2][4];
#pragma unroll
        for (int i = 0; i < 2; ++i) ldsm4(ah[i], aH + aoff + i * 16 * ROWB + ko);
#pragma unroll
        for (int i = 0; i < 2; ++i) ldsm4(al[i], aL + aoff + i * 16 * ROWB + ko);
#pragma unroll
        for (int i = 0; i < 2; ++i) {
#pragma unroll
            for (int j = 0; j < 4; ++j) {
                const uint32_t b0 = bt[j >> 1][(j & 1) * 2];
                const uint32_t b1 = bt[j >> 1][(j & 1) * 2 + 1];
                mma_bf16(c[i][j], ah[i], b0, b1);   // hi and lo share one f32 accumulator
                mma_bf16(c[i][j], al[i], b0, b1);
            }
        }
    }
}

__global__ void __launch_bounds__(THREADS, 1)
gemm_kernel(const float* __restrict__ scale, const float* __restrict__ bias,
            float* __restrict__ out) {
    extern __shared__ char smem[];
    const uint32_t sb = smem_u32(smem);
    const int tid = threadIdx.x;
    const int wid = tid >> 5;        // 0..15
    const int l = tid & 31;

    const int mt = blockIdx.x;   // fastest -> consecutive CTAs share W tile via L2
    const int nt = blockIdx.y;
    const size_t mBase = (size_t)mt * BM;
    const size_t nBase = (size_t)nt * BN;

    const __nv_bfloat16* Ah = g_xh + mBase * K_DIM;
    const __nv_bfloat16* Al = g_xl + mBase * K_DIM;
    const __nv_bfloat16* Bw = g_w + nBase * K_DIM;

    const int wm = (wid & 3) * 32;   // 4x4 warp grid, 32x32 warp tile
    const int wn = (wid >> 2) * 32;

    float c[2][4][4];                // 32 f32 accumulators (hi+lo fused)
#pragma unroll
    for (int i = 0; i < 2; ++i)
#pragma unroll
        for (int j = 0; j < 4; ++j)
#pragma unroll
            for (int k = 0; k < 4; ++k) c[i][j][k] = 0.0f;

    // prologue: stages 0..1
#pragma unroll
    for (int s = 0; s < STAGES - 1; ++s) {
        load_stage(sb + s * STAGE_BYTES, Ah, Al, Bw, s, tid);
        CP_COMMIT();
    }

    for (int it = 0; it < NITER; ++it) {
        CP_WAIT(STAGES - 2);
        __syncthreads();
        if (it + STAGES - 1 < NITER)
            load_stage(sb + ((it + STAGES - 1) % STAGES) * STAGE_BYTES,
                       Ah, Al, Bw, it + STAGES - 1, tid);
        CP_COMMIT();   // always commit so wait-count stays aligned in the tail
        tile_compute(sb + (it % STAGES) * STAGE_BYTES, l, wm, wn, c);
    }

    // ---------------- epilogue: scale + bias + exact GELU ----------------
    const int gid = l >> 2, tig = l & 3;

    float wv[8], bv[8];
#pragma unroll
    for (int j = 0; j < 4; ++j) {
        const size_t n0 = nBase + wn + 8 * j + 2 * tig;
        wv[2 * j] = scale[n0]; wv[2 * j + 1] = scale[n0 + 1];
        bv[2 * j] = bias[n0];  bv[2 * j + 1] = bias[n0 + 1];
    }

#pragma unroll
    for (int i = 0; i < 2; ++i) {
#pragma unroll
        for (int j = 0; j < 4; ++j) {
            const size_t n0 = nBase + wn + 8 * j + 2 * tig;
#pragma unroll
            for (int h = 0; h < 2; ++h) {
                const size_t m = mBase + wm + 16 * i + gid + 8 * h;
                float y0 = fmaf(c[i][j][2 * h],     wv[2 * j],     bv[2 * j]);
                float y1 = fmaf(c[i][j][2 * h + 1], wv[2 * j + 1], bv[2 * j + 1]);
                float g0 = 0.5f * y0 * (1.0f + erff(y0 * 0.70710678118654752f));
                float g1 = 0.5f * y1 * (1.0f + erff(y1 * 0.70710678118654752f));
                float2 vv; vv.x = g0; vv.y = g1;
                __stcg(reinterpret_cast<float2*>(out + m * N_DIM + n0), vv);  // bypass L2
            }
        }
    }
}

// ---------------- launch ----------------
extern "C" void kernel_launch(void* const* d_in, const int* in_sizes, int n_in,
                              void* d_out, int out_size) {
    const float* x     = (const float*)d_in[0];
    const int*   Wq    = (const int*)d_in[1];
    const float* scale = (const float*)d_in[2];
    const float* bias  = (const float*)d_in[3];
    float* out = (float*)d_out;
    (void)in_sizes; (void)n_in; (void)out_size;

    // x -> bf16 hi/residual planes
    {
        const int n4 = (M_DIM * K_DIM) / 4;   // 8388608
        cvt_x_kernel<<<(n4 + 255) / 256, 256>>>((const float4*)x, n4);
    }
    // Wq int32 -> bf16 (exact)
    {
        const int n4 = (N_DIM * K_DIM) / 4;   // 11272192
        cvt_w_kernel<<<(n4 + 255) / 256, 256>>>((const int4*)Wq, n4);
    }
    // GEMM + fused epilogue
    cudaFuncSetAttribute(gemm_kernel, cudaFuncAttributeMaxDynamicSharedMemorySize,
                         SMEM_BYTES);
    dim3 grid(M_DIM / BM, N_DIM / BN);        // (64, 86), mt fastest
    gemm_kernel<<<grid, THREADS, SMEM_BYTES>>>(scale, bias, out);
}

// round 9
// speedup vs baseline: 3.1103x; 1.1847x over previous
#include <cuda_runtime.h>
#include <cuda_bf16.h>
#include <cstdint>
#include <cstddef>

// Problem dims
#define M_DIM 8192
#define K_DIM 4096
#define N_DIM 11008

// GEMM tiling (bf16 dual-plane, legacy HMMA path)
#define BM 256
#define BN 128
#define BKE 64                  // K elements (bf16) per stage = 128 bytes per row
#define STAGES 2
#define NITER (K_DIM / BKE)     // 64
#define THREADS 512             // 16 warps, 4(m) x 4(n) warp grid, 64x32 warp tile
#define ROWBYTES 128            // XOR-swizzled rows, no padding
#define TILE_A (BM * ROWBYTES)              // 32768 (per A plane)
#define TILE_W (BN * ROWBYTES)              // 16384
#define STAGE_BYTES (2 * TILE_A + TILE_W)   // 81920: Ahi | Alo | W
#define SMEM_BYTES (STAGES * STAGE_BYTES)   // 163840

// Scratch (device globals — no runtime allocation allowed)
__device__ __nv_bfloat16 g_xh[(size_t)M_DIM * K_DIM];   // x hi plane (bf16)
__device__ __nv_bfloat16 g_xl[(size_t)M_DIM * K_DIM];   // x residual plane (bf16)
__device__ __nv_bfloat16 g_w [(size_t)N_DIM * K_DIM];   // Wq as bf16 (exact)

// ---------------- PTX helpers (portable ISA only: sm_80+) ----------------
__device__ __forceinline__ uint32_t smem_u32(const void* p) {
    uint32_t a;
    asm("{ .reg .u64 t; cvta.to.shared.u64 t, %1; cvt.u32.u64 %0, t; }"
        : "=r"(a) : "l"(p));
    return a;
}
__device__ __forceinline__ void cp16(uint32_t s, const void* g) {
    asm volatile("cp.async.cg.shared.global [%0], [%1], 16;" :: "r"(s), "l"(g) : "memory");
}
#define CP_COMMIT() asm volatile("cp.async.commit_group;" ::: "memory")
#define CP_WAIT(n)  asm volatile("cp.async.wait_group %0;" :: "n"(n) : "memory")

__device__ __forceinline__ void ldsm4(uint32_t* d, uint32_t addr) {
    asm volatile("ldmatrix.sync.aligned.m8n8.x4.shared.b16 {%0,%1,%2,%3}, [%4];"
                 : "=r"(d[0]), "=r"(d[1]), "=r"(d[2]), "=r"(d[3]) : "r"(addr));
}
// C(f32) += A(16x16 bf16) * B(16x8 bf16)^T
__device__ __forceinline__ void mma_bf16(float* c, const uint32_t* a, uint32_t b0, uint32_t b1) {
    asm volatile(
        "mma.sync.aligned.m16n8k16.row.col.f32.bf16.bf16.f32 "
        "{%0,%1,%2,%3},{%4,%5,%6,%7},{%8,%9},{%0,%1,%2,%3};"
        : "+f"(c[0]), "+f"(c[1]), "+f"(c[2]), "+f"(c[3])
        : "r"(a[0]), "r"(a[1]), "r"(a[2]), "r"(a[3]), "r"(b0), "r"(b1));
}

// ---------------- prepass 1: x -> bf16 hi + bf16 residual ----------------
__device__ __forceinline__ uint32_t pack_bf2(float a, float b) {
    __nv_bfloat162 t = __floats2bfloat162_rn(a, b);
    return *reinterpret_cast<uint32_t*>(&t);
}
__global__ void cvt_x_kernel(const float4* __restrict__ x, int n4) {
    int i = blockIdx.x * blockDim.x + threadIdx.x;
    if (i >= n4) return;
    float4 v = x[i];
    float h0 = __bfloat162float(__float2bfloat16(v.x));
    float h1 = __bfloat162float(__float2bfloat16(v.y));
    float h2 = __bfloat162float(__float2bfloat16(v.z));
    float h3 = __bfloat162float(__float2bfloat16(v.w));
    uint2 hi = make_uint2(pack_bf2(v.x, v.y), pack_bf2(v.z, v.w));
    uint2 lo = make_uint2(pack_bf2(v.x - h0, v.y - h1), pack_bf2(v.z - h2, v.w - h3));
    reinterpret_cast<uint2*>(g_xh)[i] = hi;
    reinterpret_cast<uint2*>(g_xl)[i] = lo;
}

// ---------------- prepass 2: Wq int32 -> bf16 (exact for |w|<=127) ----------------
__global__ void cvt_w_kernel(const int4* __restrict__ wq, int n4) {
    int i = blockIdx.x * blockDim.x + threadIdx.x;
    if (i >= n4) return;
    int4 q = wq[i];
    uint2 o = make_uint2(pack_bf2((float)q.x, (float)q.y), pack_bf2((float)q.z, (float)q.w));
    reinterpret_cast<uint2*>(g_w)[i] = o;
}

// ---------------- GEMM ----------------
// XOR swizzle: row r (128B), 16B chunk c stored at chunk (c ^ (r&7))
__device__ __forceinline__ void load_stage(uint32_t sbase,
                                           const __nv_bfloat16* __restrict__ Ah,
                                           const __nv_bfloat16* __restrict__ Al,
                                           const __nv_bfloat16* __restrict__ Bw,
                                           int kc, int tid) {
    const int kb = kc * BKE;
    // A planes: 256 rows x 8 chunks = 2048 chunks each; 4 per thread per plane
#pragma unroll
    for (int i = 0; i < 4; ++i) {
        const int q = i * THREADS + tid;
        const int r = q >> 3, c = q & 7;
        const uint32_t so = (uint32_t)r * ROWBYTES + ((c ^ (r & 7)) << 4);
        const size_t ge = (size_t)r * K_DIM + kb + c * 8;
        cp16(sbase + so,          Ah + ge);
        cp16(sbase + TILE_A + so, Al + ge);
    }
    // W: 128 rows x 8 chunks = 1024 chunks; 2 per thread
#pragma unroll
    for (int i = 0; i < 2; ++i) {
        const int q = i * THREADS + tid;
        const int r = q >> 3, c = q & 7;
        const uint32_t so = (uint32_t)r * ROWBYTES + ((c ^ (r & 7)) << 4);
        const size_t ge = (size_t)r * K_DIM + kb + c * 8;
        cp16(sbase + 2 * TILE_A + so, Bw + ge);
    }
}

__device__ __forceinline__ void tile_compute(uint32_t st, int l, int wm, int wn,
                                             float c[4][4][4]) {
    const uint32_t aH = st;
    const uint32_t aL = st + TILE_A;
    const uint32_t bB = st + 2 * TILE_A;
    const int r = l & 7, mi = l >> 3;

    // A fragment rows: mat bit0 -> +8 rows, bit1 -> +16B (chunk+1)
    const int arow = ((mi & 1) << 3) + r;
    const int ac0 = (mi >> 1);
    uint32_t aBase[4]; int ax[4];
#pragma unroll
    for (int i = 0; i < 4; ++i) {
        const int rowi = wm + arow + 16 * i;
        aBase[i] = (uint32_t)rowi * ROWBYTES;
        ax[i] = rowi & 7;
    }
    // B fragment rows (W stored [n][k]): mat bit1 -> +8 n-rows, bit0 -> +16B
    const int brow = wn + ((mi >> 1) << 3) + r;
    const int bc0 = (mi & 1);
    const uint32_t bBase0 = (uint32_t)brow * ROWBYTES;
    const uint32_t bBase1 = (uint32_t)(brow + 16) * ROWBYTES;
    const int bx = brow & 7;   // (brow+16)&7 == brow&7

#pragma unroll
    for (int ks = 0; ks < 4; ++ks) {
        const int ca = ac0 + 2 * ks;   // A chunk index for this k-step
        const int cb = bc0 + 2 * ks;   // B chunk index
        uint32_t bt0[4], bt1[4];
        ldsm4(bt0, bB + bBase0 + (uint32_t)((cb ^ bx) << 4));   // n 0..15
        ldsm4(bt1, bB + bBase1 + (uint32_t)((cb ^ bx) << 4));   // n 16..31

        uint32_t a[4][4];
        // hi plane
#pragma unroll
        for (int i = 0; i < 4; ++i)
            ldsm4(a[i], aH + aBase[i] + (uint32_t)((ca ^ ax[i]) << 4));
#pragma unroll
        for (int i = 0; i < 4; ++i) {
#pragma unroll
            for (int j = 0; j < 4; ++j) {
                const uint32_t* bt = (j < 2) ? bt0 : bt1;
                mma_bf16(c[i][j], a[i], bt[(j & 1) * 2], bt[(j & 1) * 2 + 1]);
            }
        }
        // lo plane (reuse fragment registers, same f32 accumulators)
#pragma unroll
        for (int i = 0; i < 4; ++i)
            ldsm4(a[i], aL + aBase[i] + (uint32_t)((ca ^ ax[i]) << 4));
#pragma unroll
        for (int i = 0; i < 4; ++i) {
#pragma unroll
            for (int j = 0; j < 4; ++j) {
                const uint32_t* bt = (j < 2) ? bt0 : bt1;
                mma_bf16(c[i][j], a[i], bt[(j & 1) * 2], bt[(j & 1) * 2 + 1]);
            }
        }
    }
}

__global__ void __launch_bounds__(THREADS, 1)
gemm_kernel(const float* __restrict__ scale, const float* __restrict__ bias,
            float* __restrict__ out) {
    extern __shared__ char smem[];
    const uint32_t sb = smem_u32(smem);
    const int tid = threadIdx.x;
    const int wid = tid >> 5;        // 0..15
    const int l = tid & 31;

    const int nt = blockIdx.x;   // fastest -> W (90MB) stays L2-resident across mt sweep
    const int mt = blockIdx.y;
    const size_t mBase = (size_t)mt * BM;
    const size_t nBase = (size_t)nt * BN;

    const __nv_bfloat16* Ah = g_xh + mBase * K_DIM;
    const __nv_bfloat16* Al = g_xl + mBase * K_DIM;
    const __nv_bfloat16* Bw = g_w + nBase * K_DIM;

    const int wm = (wid & 3) * 64;   // 4x4 warp grid, 64x32 warp tile
    const int wn = (wid >> 2) * 32;

    float c[4][4][4];                // 64 f32 accumulators (hi+lo fused)
#pragma unroll
    for (int i = 0; i < 4; ++i)
#pragma unroll
        for (int j = 0; j < 4; ++j)
#pragma unroll
            for (int k = 0; k < 4; ++k) c[i][j][k] = 0.0f;

    // prologue: stage 0
    load_stage(sb, Ah, Al, Bw, 0, tid);
    CP_COMMIT();

    for (int it = 0; it < NITER; ++it) {
        if (it + 1 < NITER)
            load_stage(sb + ((it + 1) & 1) * STAGE_BYTES, Ah, Al, Bw, it + 1, tid);
        CP_COMMIT();          // empty group in tail keeps counts aligned
        CP_WAIT(1);           // stage `it` data resident
        __syncthreads();
        tile_compute(sb + (it & 1) * STAGE_BYTES, l, wm, wn, c);
        __syncthreads();      // all warps done before this buffer is overwritten
    }

    // ---------------- epilogue: scale + bias + exact GELU ----------------
    const int gid = l >> 2, tig = l & 3;

    float wv[8], bv[8];
#pragma unroll
    for (int j = 0; j < 4; ++j) {
        const size_t n0 = nBase + wn + 8 * j + 2 * tig;
        wv[2 * j] = scale[n0]; wv[2 * j + 1] = scale[n0 + 1];
        bv[2 * j] = bias[n0];  bv[2 * j + 1] = bias[n0 + 1];
    }

#pragma unroll
    for (int i = 0; i < 4; ++i) {
#pragma unroll
        for (int j = 0; j < 4; ++j) {
            const size_t n0 = nBase + wn + 8 * j + 2 * tig;
#pragma unroll
            for (int h = 0; h < 2; ++h) {
                const size_t m = mBase + wm + 16 * i + gid + 8 * h;
                float y0 = fmaf(c[i][j][2 * h],     wv[2 * j],     bv[2 * j]);
                float y1 = fmaf(c[i][j][2 * h + 1], wv[2 * j + 1], bv[2 * j + 1]);
                float g0 = 0.5f * y0 * (1.0f + erff(y0 * 0.70710678118654752f));
                float g1 = 0.5f * y1 * (1.0f + erff(y1 * 0.70710678118654752f));
                float2 vv; vv.x = g0; vv.y = g1;
                __stcg(reinterpret_cast<float2*>(out + m * N_DIM + n0), vv);
            }
        }
    }
}

// ---------------- launch ----------------
extern "C" void kernel_launch(void* const* d_in, const int* in_sizes, int n_in,
                              void* d_out, int out_size) {
    const float* x     = (const float*)d_in[0];
    const int*   Wq    = (const int*)d_in[1];
    const float* scale = (const float*)d_in[2];
    const float* bias  = (const float*)d_in[3];
    float* out = (float*)d_out;
    (void)in_sizes; (void)n_in; (void)out_size;

    // x -> bf16 hi/residual planes
    {
        const int n4 = (M_DIM * K_DIM) / 4;   // 8388608
        cvt_x_kernel<<<(n4 + 255) / 256, 256>>>((const float4*)x, n4);
    }
    // Wq int32 -> bf16 (exact)
    {
        const int n4 = (N_DIM * K_DIM) / 4;   // 11272192
        cvt_w_kernel<<<(n4 + 255) / 256, 256>>>((const int4*)Wq, n4);
    }
    // GEMM + fused epilogue
    cudaFuncSetAttribute(gemm_kernel, cudaFuncAttributeMaxDynamicSharedMemorySize,
                         SMEM_BYTES);
    dim3 grid(N_DIM / BN, M_DIM / BM);        // (86, 32), nt fastest
    gemm_kernel<<<grid, THREADS, SMEM_BYTES>>>(scale, bias, out);
}

// round 10
// speedup vs baseline: 5.4223x; 1.7434x over previous
#include <cuda_runtime.h>
#include <cuda_fp16.h>
#include <cstdint>
#include <cstddef>

// Problem dims
#define M_DIM 8192
#define K_DIM 4096
#define N_DIM 11008

// GEMM tiling (single-plane fp16, legacy HMMA path, rt_SMSP(HMMA)~8)
#define BM 256
#define BN 128
#define BKE 64                  // K elements (fp16) per stage = 128 bytes per row
#define STAGES 4
#define NITER (K_DIM / BKE)     // 64
#define THREADS 512             // 16 warps, 4(m) x 4(n) warp grid, 64x32 warp tile
#define ROWBYTES 128            // XOR-swizzled rows, no padding
#define TILE_A (BM * ROWBYTES)              // 32768
#define TILE_W (BN * ROWBYTES)              // 16384
#define STAGE_BYTES (TILE_A + TILE_W)       // 49152: A | W
#define SMEM_BYTES (STAGES * STAGE_BYTES)   // 196608

// Scratch (device globals — no runtime allocation allowed)
__device__ __half g_xh[(size_t)M_DIM * K_DIM];   // x as fp16 (11-bit mantissa)
__device__ __half g_w [(size_t)N_DIM * K_DIM];   // Wq as fp16 (exact, |w|<=127)

// ---------------- PTX helpers (portable ISA only: sm_80+) ----------------
__device__ __forceinline__ uint32_t smem_u32(const void* p) {
    uint32_t a;
    asm("{ .reg .u64 t; cvta.to.shared.u64 t, %1; cvt.u32.u64 %0, t; }"
        : "=r"(a) : "l"(p));
    return a;
}
__device__ __forceinline__ void cp16(uint32_t s, const void* g) {
    asm volatile("cp.async.cg.shared.global [%0], [%1], 16;" :: "r"(s), "l"(g) : "memory");
}
#define CP_COMMIT() asm volatile("cp.async.commit_group;" ::: "memory")
#define CP_WAIT(n)  asm volatile("cp.async.wait_group %0;" :: "n"(n) : "memory")

__device__ __forceinline__ void ldsm4(uint32_t* d, uint32_t addr) {
    asm volatile("ldmatrix.sync.aligned.m8n8.x4.shared.b16 {%0,%1,%2,%3}, [%4];"
                 : "=r"(d[0]), "=r"(d[1]), "=r"(d[2]), "=r"(d[3]) : "r"(addr));
}
// C(f32) += A(16x16 f16) * B(16x8 f16)^T
__device__ __forceinline__ void mma_f16(float* c, const uint32_t* a, uint32_t b0, uint32_t b1) {
    asm volatile(
        "mma.sync.aligned.m16n8k16.row.col.f32.f16.f16.f32 "
        "{%0,%1,%2,%3},{%4,%5,%6,%7},{%8,%9},{%0,%1,%2,%3};"
        : "+f"(c[0]), "+f"(c[1]), "+f"(c[2]), "+f"(c[3])
        : "r"(a[0]), "r"(a[1]), "r"(a[2]), "r"(a[3]), "r"(b0), "r"(b1));
}

// ---------------- prepass 1: x -> fp16 ----------------
__global__ void cvt_x_kernel(const float4* __restrict__ x, int n4) {
    int i = blockIdx.x * blockDim.x + threadIdx.x;
    if (i >= n4) return;
    float4 v = x[i];
    __half2 a = __floats2half2_rn(v.x, v.y);
    __half2 b = __floats2half2_rn(v.z, v.w);
    uint2 o = make_uint2(*reinterpret_cast<uint32_t*>(&a), *reinterpret_cast<uint32_t*>(&b));
    reinterpret_cast<uint2*>(g_xh)[i] = o;
}

// ---------------- prepass 2: Wq int32 -> fp16 (exact for |w|<=127) ----------------
__global__ void cvt_w_kernel(const int4* __restrict__ wq, int n4) {
    int i = blockIdx.x * blockDim.x + threadIdx.x;
    if (i >= n4) return;
    int4 q = wq[i];
    __half2 a = __floats2half2_rn((float)q.x, (float)q.y);
    __half2 b = __floats2half2_rn((float)q.z, (float)q.w);
    uint2 o = make_uint2(*reinterpret_cast<uint32_t*>(&a), *reinterpret_cast<uint32_t*>(&b));
    reinterpret_cast<uint2*>(g_w)[i] = o;
}

// ---------------- GEMM ----------------
// XOR swizzle: row r (128B), 16B chunk c stored at chunk (c ^ (r&7))
__device__ __forceinline__ void load_stage(uint32_t sbase,
                                           const __half* __restrict__ Ax,
                                           const __half* __restrict__ Bw,
                                           int kc, int tid) {
    const int kb = kc * BKE;
    // A: 256 rows x 8 chunks = 2048 chunks; 4 per thread
#pragma unroll
    for (int i = 0; i < 4; ++i) {
        const int q = i * THREADS + tid;
        const int r = q >> 3, c = q & 7;
        const uint32_t so = (uint32_t)r * ROWBYTES + ((c ^ (r & 7)) << 4);
        const size_t ge = (size_t)r * K_DIM + kb + c * 8;
        cp16(sbase + so, Ax + ge);
    }
    // W: 128 rows x 8 chunks = 1024 chunks; 2 per thread
#pragma unroll
    for (int i = 0; i < 2; ++i) {
        const int q = i * THREADS + tid;
        const int r = q >> 3, c = q & 7;
        const uint32_t so = (uint32_t)r * ROWBYTES + ((c ^ (r & 7)) << 4);
        const size_t ge = (size_t)r * K_DIM + kb + c * 8;
        cp16(sbase + TILE_A + so, Bw + ge);
    }
}

__device__ __forceinline__ void tile_compute(uint32_t st, int l, int wm, int wn,
                                             float c[4][4][4]) {
    const uint32_t aB = st;
    const uint32_t bB = st + TILE_A;
    const int r = l & 7, mi = l >> 3;

    // A fragment rows: mat bit0 -> +8 rows, bit1 -> +16B (chunk+1)
    const int arow = ((mi & 1) << 3) + r;
    const int ac0 = (mi >> 1);
    uint32_t aBase[4]; int ax[4];
#pragma unroll
    for (int i = 0; i < 4; ++i) {
        const int rowi = wm + arow + 16 * i;
        aBase[i] = (uint32_t)rowi * ROWBYTES;
        ax[i] = rowi & 7;
    }
    // B fragment rows (W stored [n][k]): mat bit1 -> +8 n-rows, bit0 -> +16B
    const int brow = wn + ((mi >> 1) << 3) + r;
    const int bc0 = (mi & 1);
    const uint32_t bBase0 = (uint32_t)brow * ROWBYTES;
    const uint32_t bBase1 = (uint32_t)(brow + 16) * ROWBYTES;
    const int bx = brow & 7;   // (brow+16)&7 == brow&7

#pragma unroll
    for (int ks = 0; ks < 4; ++ks) {
        const int ca = ac0 + 2 * ks;   // A chunk index for this k-step
        const int cb = bc0 + 2 * ks;   // B chunk index
        uint32_t bt0[4], bt1[4];
        ldsm4(bt0, bB + bBase0 + (uint32_t)((cb ^ bx) << 4));   // n 0..15
        ldsm4(bt1, bB + bBase1 + (uint32_t)((cb ^ bx) << 4));   // n 16..31

        uint32_t a[4][4];
#pragma unroll
        for (int i = 0; i < 4; ++i)
            ldsm4(a[i], aB + aBase[i] + (uint32_t)((ca ^ ax[i]) << 4));
#pragma unroll
        for (int i = 0; i < 4; ++i) {
#pragma unroll
            for (int j = 0; j < 4; ++j) {
                const uint32_t* bt = (j < 2) ? bt0 : bt1;
                mma_f16(c[i][j], a[i], bt[(j & 1) * 2], bt[(j & 1) * 2 + 1]);
            }
        }
    }
}

__global__ void __launch_bounds__(THREADS, 1)
gemm_kernel(const float* __restrict__ scale, const float* __restrict__ bias,
            float* __restrict__ out) {
    extern __shared__ char smem[];
    const uint32_t sb = smem_u32(smem);
    const int tid = threadIdx.x;
    const int wid = tid >> 5;        // 0..15
    const int l = tid & 31;

    const int nt = blockIdx.x;   // fastest -> W (90MB) stays L2-resident across mt sweep
    const int mt = blockIdx.y;
    const size_t mBase = (size_t)mt * BM;
    const size_t nBase = (size_t)nt * BN;

    const __half* Ax = g_xh + mBase * K_DIM;
    const __half* Bw = g_w + nBase * K_DIM;

    const int wm = (wid & 3) * 64;   // 4x4 warp grid, 64x32 warp tile
    const int wn = (wid >> 2) * 32;

    float c[4][4][4];                // 64 f32 accumulators
#pragma unroll
    for (int i = 0; i < 4; ++i)
#pragma unroll
        for (int j = 0; j < 4; ++j)
#pragma unroll
            for (int k = 0; k < 4; ++k) c[i][j][k] = 0.0f;

    // prologue: stages 0..2
#pragma unroll
    for (int s = 0; s < STAGES - 1; ++s) {
        load_stage(sb + s * STAGE_BYTES, Ax, Bw, s, tid);
        CP_COMMIT();
    }

    for (int it = 0; it < NITER; ++it) {
        CP_WAIT(STAGES - 2);       // stage `it` resident
        __syncthreads();           // also: all warps done with stage it-1 buffers
        if (it + STAGES - 1 < NITER)
            load_stage(sb + ((it + STAGES - 1) & 3) * STAGE_BYTES,
                       Ax, Bw, it + STAGES - 1, tid);
        CP_COMMIT();               // empty group in tail keeps counts aligned
        tile_compute(sb + (it & 3) * STAGE_BYTES, l, wm, wn, c);
    }

    // ---------------- epilogue: scale + bias + exact GELU ----------------
    const int gid = l >> 2, tig = l & 3;

    float wv[8], bv[8];
#pragma unroll
    for (int j = 0; j < 4; ++j) {
        const size_t n0 = nBase + wn + 8 * j + 2 * tig;
        wv[2 * j] = scale[n0]; wv[2 * j + 1] = scale[n0 + 1];
        bv[2 * j] = bias[n0];  bv[2 * j + 1] = bias[n0 + 1];
    }

#pragma unroll
    for (int i = 0; i < 4; ++i) {
#pragma unroll
        for (int j = 0; j < 4; ++j) {
            const size_t n0 = nBase + wn + 8 * j + 2 * tig;
#pragma unroll
            for (int h = 0; h < 2; ++h) {
                const size_t m = mBase + wm + 16 * i + gid + 8 * h;
                float y0 = fmaf(c[i][j][2 * h],     wv[2 * j],     bv[2 * j]);
                float y1 = fmaf(c[i][j][2 * h + 1], wv[2 * j + 1], bv[2 * j + 1]);
                float g0 = 0.5f * y0 * (1.0f + erff(y0 * 0.70710678118654752f));
                float g1 = 0.5f * y1 * (1.0f + erff(y1 * 0.70710678118654752f));
                float2 vv; vv.x = g0; vv.y = g1;
                __stcg(reinterpret_cast<float2*>(out + m * N_DIM + n0), vv);
            }
        }
    }
}

// ---------------- launch ----------------
extern "C" void kernel_launch(void* const* d_in, const int* in_sizes, int n_in,
                              void* d_out, int out_size) {
    const float* x     = (const float*)d_in[0];
    const int*   Wq    = (const int*)d_in[1];
    const float* scale = (const float*)d_in[2];
    const float* bias  = (const float*)d_in[3];
    float* out = (float*)d_out;
    (void)in_sizes; (void)n_in; (void)out_size;

    // x -> fp16
    {
        const int n4 = (M_DIM * K_DIM) / 4;   // 8388608
        cvt_x_kernel<<<(n4 + 255) / 256, 256>>>((const float4*)x, n4);
    }
    // Wq int32 -> fp16 (exact)
    {
        const int n4 = (N_DIM * K_DIM) / 4;   // 11272192
        cvt_w_kernel<<<(n4 + 255) / 256, 256>>>((const int4*)Wq, n4);
    }
    // GEMM + fused epilogue
    cudaFuncSetAttribute(gemm_kernel, cudaFuncAttributeMaxDynamicSharedMemorySize,
                         SMEM_BYTES);
    dim3 grid(N_DIM / BN, M_DIM / BM);        // (86, 32), nt fastest
    gemm_kernel<<<grid, THREADS, SMEM_BYTES>>>(scale, bias, out);
}

// round 11
// speedup vs baseline: 5.4897x; 1.0124x over previous
#include <cuda_runtime.h>
#include <cuda_fp16.h>
#include <cstdint>
#include <cstddef>

// Problem dims
#define M_DIM 8192
#define K_DIM 4096
#define N_DIM 11008

// GEMM tiling (single-plane fp16, legacy HMMA, rt_SMSP~8; smem-traffic-optimized)
#define BM 256
#define BN 128
#define BKE 64                  // K elements (fp16) per stage = 128 bytes per row
#define STAGES 4
#define NITER (K_DIM / BKE)     // 64
#define THREADS 256             // 8 warps, 4(m) x 2(n) grid, 64x64 warp tile
#define ROWBYTES 128            // XOR-swizzled rows, no padding
#define TILE_A (BM * ROWBYTES)              // 32768
#define TILE_W (BN * ROWBYTES)              // 16384
#define STAGE_BYTES (TILE_A + TILE_W)       // 49152: A | W
#define SMEM_BYTES (STAGES * STAGE_BYTES)   // 196608

// Scratch (device globals — no runtime allocation allowed)
__device__ __half g_xh[(size_t)M_DIM * K_DIM];   // x as fp16 (11-bit mantissa)
__device__ __half g_w [(size_t)N_DIM * K_DIM];   // Wq as fp16 (exact, |w|<=127)

// ---------------- PTX helpers (portable ISA only: sm_80+) ----------------
__device__ __forceinline__ uint32_t smem_u32(const void* p) {
    uint32_t a;
    asm("{ .reg .u64 t; cvta.to.shared.u64 t, %1; cvt.u32.u64 %0, t; }"
        : "=r"(a) : "l"(p));
    return a;
}
__device__ __forceinline__ void cp16(uint32_t s, const void* g) {
    asm volatile("cp.async.cg.shared.global [%0], [%1], 16;" :: "r"(s), "l"(g) : "memory");
}
#define CP_COMMIT() asm volatile("cp.async.commit_group;" ::: "memory")
#define CP_WAIT(n)  asm volatile("cp.async.wait_group %0;" :: "n"(n) : "memory")

__device__ __forceinline__ void ldsm4(uint32_t* d, uint32_t addr) {
    asm volatile("ldmatrix.sync.aligned.m8n8.x4.shared.b16 {%0,%1,%2,%3}, [%4];"
                 : "=r"(d[0]), "=r"(d[1]), "=r"(d[2]), "=r"(d[3]) : "r"(addr));
}
// C(f32) += A(16x16 f16) * B(16x8 f16)^T
__device__ __forceinline__ void mma_f16(float* c, const uint32_t* a, uint32_t b0, uint32_t b1) {
    asm volatile(
        "mma.sync.aligned.m16n8k16.row.col.f32.f16.f16.f32 "
        "{%0,%1,%2,%3},{%4,%5,%6,%7},{%8,%9},{%0,%1,%2,%3};"
        : "+f"(c[0]), "+f"(c[1]), "+f"(c[2]), "+f"(c[3])
        : "r"(a[0]), "r"(a[1]), "r"(a[2]), "r"(a[3]), "r"(b0), "r"(b1));
}

// ---------------- prepass 1: x -> fp16 ----------------
__global__ void cvt_x_kernel(const float4* __restrict__ x, int n4) {
    int i = blockIdx.x * blockDim.x + threadIdx.x;
    if (i >= n4) return;
    float4 v = x[i];
    __half2 a = __floats2half2_rn(v.x, v.y);
    __half2 b = __floats2half2_rn(v.z, v.w);
    uint2 o = make_uint2(*reinterpret_cast<uint32_t*>(&a), *reinterpret_cast<uint32_t*>(&b));
    reinterpret_cast<uint2*>(g_xh)[i] = o;
}

// ---------------- prepass 2: Wq int32 -> fp16 (exact for |w|<=127) ----------------
__global__ void cvt_w_kernel(const int4* __restrict__ wq, int n4) {
    int i = blockIdx.x * blockDim.x + threadIdx.x;
    if (i >= n4) return;
    int4 q = wq[i];
    __half2 a = __floats2half2_rn((float)q.x, (float)q.y);
    __half2 b = __floats2half2_rn((float)q.z, (float)q.w);
    uint2 o = make_uint2(*reinterpret_cast<uint32_t*>(&a), *reinterpret_cast<uint32_t*>(&b));
    reinterpret_cast<uint2*>(g_w)[i] = o;
}

// ---------------- GEMM ----------------
// XOR swizzle: row r (128B), 16B chunk c stored at chunk (c ^ (r&7))
__device__ __forceinline__ void load_stage(uint32_t sbase,
                                           const __half* __restrict__ Ax,
                                           const __half* __restrict__ Bw,
                                           int kc, int tid) {
    const int kb = kc * BKE;
    // A: 256 rows x 8 chunks = 2048 chunks; 8 per thread
#pragma unroll
    for (int i = 0; i < 8; ++i) {
        const int q = i * THREADS + tid;
        const int r = q >> 3, c = q & 7;
        const uint32_t so = (uint32_t)r * ROWBYTES + ((c ^ (r & 7)) << 4);
        const size_t ge = (size_t)r * K_DIM + kb + c * 8;
        cp16(sbase + so, Ax + ge);
    }
    // W: 128 rows x 8 chunks = 1024 chunks; 4 per thread
#pragma unroll
    for (int i = 0; i < 4; ++i) {
        const int q = i * THREADS + tid;
        const int r = q >> 3, c = q & 7;
        const uint32_t so = (uint32_t)r * ROWBYTES + ((c ^ (r & 7)) << 4);
        const size_t ge = (size_t)r * K_DIM + kb + c * 8;
        cp16(sbase + TILE_A + so, Bw + ge);
    }
}

__device__ __forceinline__ void tile_compute(uint32_t st, int l, int wm, int wn,
                                             float c[4][8][4]) {
    const uint32_t aB = st;
    const uint32_t bB = st + TILE_A;
    const int r = l & 7, mi = l >> 3;

    // A fragment rows: mat bit0 -> +8 rows, bit1 -> +16B (chunk+1)
    const int arow = ((mi & 1) << 3) + r;
    const int ac0 = (mi >> 1);
    uint32_t aBase[4]; int ax[4];
#pragma unroll
    for (int i = 0; i < 4; ++i) {
        const int rowi = wm + arow + 16 * i;
        aBase[i] = (uint32_t)rowi * ROWBYTES;
        ax[i] = rowi & 7;
    }
    // B fragment rows (W stored [n][k]): mat bit1 -> +8 n-rows, bit0 -> +16B
    const int brow = wn + ((mi >> 1) << 3) + r;
    const int bc0 = (mi & 1);
    uint32_t bBase[4];
#pragma unroll
    for (int nb = 0; nb < 4; ++nb)
        bBase[nb] = (uint32_t)(brow + 16 * nb) * ROWBYTES;
    const int bx = brow & 7;   // invariant under +16

#pragma unroll
    for (int ks = 0; ks < 4; ++ks) {
        const int ca = ac0 + 2 * ks;   // A chunk index for this k-step
        const int cb = bc0 + 2 * ks;   // B chunk index
        uint32_t bt[4][4];
#pragma unroll
        for (int nb = 0; nb < 4; ++nb)
            ldsm4(bt[nb], bB + bBase[nb] + (uint32_t)((cb ^ bx) << 4));  // n 16nb..16nb+15

        uint32_t a[4][4];
#pragma unroll
        for (int i = 0; i < 4; ++i)
            ldsm4(a[i], aB + aBase[i] + (uint32_t)((ca ^ ax[i]) << 4));

#pragma unroll
        for (int i = 0; i < 4; ++i) {
#pragma unroll
            for (int j = 0; j < 8; ++j) {
                mma_f16(c[i][j], a[i], bt[j >> 1][(j & 1) * 2], bt[j >> 1][(j & 1) * 2 + 1]);
            }
        }
    }
}

__global__ void __launch_bounds__(THREADS, 1)
gemm_kernel(const float* __restrict__ scale, const float* __restrict__ bias,
            float* __restrict__ out) {
    extern __shared__ char smem[];
    const uint32_t sb = smem_u32(smem);
    const int tid = threadIdx.x;
    const int wid = tid >> 5;        // 0..7
    const int l = tid & 31;

    const int nt = blockIdx.x;   // fastest -> W (90MB) stays L2-resident across mt sweep
    const int mt = blockIdx.y;
    const size_t mBase = (size_t)mt * BM;
    const size_t nBase = (size_t)nt * BN;

    const __half* Ax = g_xh + mBase * K_DIM;
    const __half* Bw = g_w + nBase * K_DIM;

    const int wm = (wid & 3) * 64;   // 4(m) x 2(n) warp grid, 64x64 warp tile
    const int wn = (wid >> 2) * 64;

    float c[4][8][4];                // 128 f32 accumulators
#pragma unroll
    for (int i = 0; i < 4; ++i)
#pragma unroll
        for (int j = 0; j < 8; ++j)
#pragma unroll
            for (int k = 0; k < 4; ++k) c[i][j][k] = 0.0f;

    // prologue: stages 0..2
#pragma unroll
    for (int s = 0; s < STAGES - 1; ++s) {
        load_stage(sb + s * STAGE_BYTES, Ax, Bw, s, tid);
        CP_COMMIT();
    }

    for (int it = 0; it < NITER; ++it) {
        CP_WAIT(STAGES - 2);       // stage `it` resident
        __syncthreads();           // also: all warps done with stage it-1 buffers
        if (it + STAGES - 1 < NITER)
            load_stage(sb + ((it + STAGES - 1) & 3) * STAGE_BYTES,
                       Ax, Bw, it + STAGES - 1, tid);
        CP_COMMIT();               // empty group in tail keeps counts aligned
        tile_compute(sb + (it & 3) * STAGE_BYTES, l, wm, wn, c);
    }

    // ---------------- epilogue: scale + bias + exact GELU ----------------
    const int gid = l >> 2, tig = l & 3;

    float wv[16], bv[16];
#pragma unroll
    for (int j = 0; j < 8; ++j) {
        const size_t n0 = nBase + wn + 8 * j + 2 * tig;
        wv[2 * j] = scale[n0]; wv[2 * j + 1] = scale[n0 + 1];
        bv[2 * j] = bias[n0];  bv[2 * j + 1] = bias[n0 + 1];
    }

#pragma unroll
    for (int i = 0; i < 4; ++i) {
#pragma unroll
        for (int j = 0; j < 8; ++j) {
            const size_t n0 = nBase + wn + 8 * j + 2 * tig;
#pragma unroll
            for (int h = 0; h < 2; ++h) {
                const size_t m = mBase + wm + 16 * i + gid + 8 * h;
                float y0 = fmaf(c[i][j][2 * h],     wv[2 * j],     bv[2 * j]);
                float y1 = fmaf(c[i][j][2 * h + 1], wv[2 * j + 1], bv[2 * j + 1]);
                float g0 = 0.5f * y0 * (1.0f + erff(y0 * 0.70710678118654752f));
                float g1 = 0.5f * y1 * (1.0f + erff(y1 * 0.70710678118654752f));
                float2 vv; vv.x = g0; vv.y = g1;
                __stcg(reinterpret_cast<float2*>(out + m * N_DIM + n0), vv);
            }
        }
    }
}

// ---------------- launch ----------------
extern "C" void kernel_launch(void* const* d_in, const int* in_sizes, int n_in,
                              void* d_out, int out_size) {
    const float* x     = (const float*)d_in[0];
    const int*   Wq    = (const int*)d_in[1];
    const float* scale = (const float*)d_in[2];
    const float* bias  = (const float*)d_in[3];
    float* out = (float*)d_out;
    (void)in_sizes; (void)n_in; (void)out_size;

    // x -> fp16
    {
        const int n4 = (M_DIM * K_DIM) / 4;   // 8388608
        cvt_x_kernel<<<(n4 + 255) / 256, 256>>>((const float4*)x, n4);
    }
    // Wq int32 -> fp16 (exact)
    {
        const int n4 = (N_DIM * K_DIM) / 4;   // 11272192
        cvt_w_kernel<<<(n4 + 255) / 256, 256>>>((const int4*)Wq, n4);
    }
    // GEMM + fused epilogue
    cudaFuncSetAttribute(gemm_kernel, cudaFuncAttributeMaxDynamicSharedMemorySize,
                         SMEM_BYTES);
    dim3 grid(N_DIM / BN, M_DIM / BM);        // (86, 32), nt fastest
    gemm_kernel<<<grid, THREADS, SMEM_BYTES>>>(scale, bias, out);
}

// round 12
// speedup vs baseline: 5.7395x; 1.0455x over previous
#include <cuda_runtime.h>
#include <cuda_fp16.h>
#include <cstdint>
#include <cstddef>

// Problem dims
#define M_DIM 8192
#define K_DIM 4096
#define N_DIM 11008

// GEMM tiling (single-plane fp16, legacy HMMA; pair-staged pipeline)
#define BM 256
#define BN 128
#define BKE 64                  // K elements (fp16) per stage = 128 bytes per row
#define NPAIR (K_DIM / (2 * BKE))   // 32 pair-iterations
#define THREADS 256             // 8 warps, 4(m) x 2(n) grid, 64x64 warp tile
#define ROWBYTES 128            // XOR-swizzled rows, no padding
#define TILE_A (BM * ROWBYTES)              // 32768
#define TILE_W (BN * ROWBYTES)              // 16384
#define STAGE_BYTES (TILE_A + TILE_W)       // 49152: A | W
#define SMEM_BYTES (4 * STAGE_BYTES)        // 196608 (2 pair-buffers)

// Scratch (device globals — no runtime allocation allowed)
__device__ __half g_xh[(size_t)M_DIM * K_DIM];   // x as fp16 (11-bit mantissa)
__device__ __half g_w [(size_t)N_DIM * K_DIM];   // Wq as fp16 (exact, |w|<=127)

// ---------------- PTX helpers (portable ISA only: sm_80+) ----------------
__device__ __forceinline__ uint32_t smem_u32(const void* p) {
    uint32_t a;
    asm("{ .reg .u64 t; cvta.to.shared.u64 t, %1; cvt.u32.u64 %0, t; }"
        : "=r"(a) : "l"(p));
    return a;
}
__device__ __forceinline__ void cp16(uint32_t s, const void* g) {
    asm volatile("cp.async.cg.shared.global [%0], [%1], 16;" :: "r"(s), "l"(g) : "memory");
}
#define CP_COMMIT() asm volatile("cp.async.commit_group;" ::: "memory")
#define CP_WAIT(n)  asm volatile("cp.async.wait_group %0;" :: "n"(n) : "memory")

__device__ __forceinline__ void ldsm4(uint32_t* d, uint32_t addr) {
    asm volatile("ldmatrix.sync.aligned.m8n8.x4.shared.b16 {%0,%1,%2,%3}, [%4];"
                 : "=r"(d[0]), "=r"(d[1]), "=r"(d[2]), "=r"(d[3]) : "r"(addr));
}
// C(f32) += A(16x16 f16) * B(16x8 f16)^T
__device__ __forceinline__ void mma_f16(float* c, const uint32_t* a, uint32_t b0, uint32_t b1) {
    asm volatile(
        "mma.sync.aligned.m16n8k16.row.col.f32.f16.f16.f32 "
        "{%0,%1,%2,%3},{%4,%5,%6,%7},{%8,%9},{%0,%1,%2,%3};"
        : "+f"(c[0]), "+f"(c[1]), "+f"(c[2]), "+f"(c[3])
        : "r"(a[0]), "r"(a[1]), "r"(a[2]), "r"(a[3]), "r"(b0), "r"(b1));
}

// ---------------- prepass 1: x -> fp16 ----------------
__global__ void cvt_x_kernel(const float4* __restrict__ x, int n4) {
    int i = blockIdx.x * blockDim.x + threadIdx.x;
    if (i >= n4) return;
    float4 v = x[i];
    __half2 a = __floats2half2_rn(v.x, v.y);
    __half2 b = __floats2half2_rn(v.z, v.w);
    uint2 o = make_uint2(*reinterpret_cast<uint32_t*>(&a), *reinterpret_cast<uint32_t*>(&b));
    reinterpret_cast<uint2*>(g_xh)[i] = o;
}

// ---------------- prepass 2: Wq int32 -> fp16 (exact for |w|<=127) ----------------
__global__ void cvt_w_kernel(const int4* __restrict__ wq, int n4) {
    int i = blockIdx.x * blockDim.x + threadIdx.x;
    if (i >= n4) return;
    int4 q = wq[i];
    __half2 a = __floats2half2_rn((float)q.x, (float)q.y);
    __half2 b = __floats2half2_rn((float)q.z, (float)q.w);
    uint2 o = make_uint2(*reinterpret_cast<uint32_t*>(&a), *reinterpret_cast<uint32_t*>(&b));
    reinterpret_cast<uint2*>(g_w)[i] = o;
}

// ---------------- GEMM ----------------
// XOR swizzle: row r (128B), 16B chunk c stored at chunk (c ^ (r&7))
__device__ __forceinline__ void load_stage(uint32_t sbase,
                                           const __half* __restrict__ Ax,
                                           const __half* __restrict__ Bw,
                                           int kc, int tid) {
    const int kb = kc * BKE;
    // A: 256 rows x 8 chunks = 2048 chunks; 8 per thread
#pragma unroll
    for (int i = 0; i < 8; ++i) {
        const int q = i * THREADS + tid;
        const int r = q >> 3, c = q & 7;
        const uint32_t so = (uint32_t)r * ROWBYTES + ((c ^ (r & 7)) << 4);
        const size_t ge = (size_t)r * K_DIM + kb + c * 8;
        cp16(sbase + so, Ax + ge);
    }
    // W: 128 rows x 8 chunks = 1024 chunks; 4 per thread
#pragma unroll
    for (int i = 0; i < 4; ++i) {
        const int q = i * THREADS + tid;
        const int r = q >> 3, c = q & 7;
        const uint32_t so = (uint32_t)r * ROWBYTES + ((c ^ (r & 7)) << 4);
        const size_t ge = (size_t)r * K_DIM + kb + c * 8;
        cp16(sbase + TILE_A + so, Bw + ge);
    }
}

__device__ __forceinline__ void tile_compute(uint32_t st, int l, int wm, int wn,
                                             float c[4][8][4]) {
    const uint32_t aB = st;
    const uint32_t bB = st + TILE_A;
    const int r = l & 7, mi = l >> 3;

    // A fragment rows: mat bit0 -> +8 rows, bit1 -> +16B (chunk+1)
    const int arow = ((mi & 1) << 3) + r;
    const int ac0 = (mi >> 1);
    uint32_t aBase[4]; int ax[4];
#pragma unroll
    for (int i = 0; i < 4; ++i) {
        const int rowi = wm + arow + 16 * i;
        aBase[i] = (uint32_t)rowi * ROWBYTES;
        ax[i] = rowi & 7;
    }
    // B fragment rows (W stored [n][k]): mat bit1 -> +8 n-rows, bit0 -> +16B
    const int brow = wn + ((mi >> 1) << 3) + r;
    const int bc0 = (mi & 1);
    uint32_t bBase[4];
#pragma unroll
    for (int nb = 0; nb < 4; ++nb)
        bBase[nb] = (uint32_t)(brow + 16 * nb) * ROWBYTES;
    const int bx = brow & 7;   // invariant under +16

#pragma unroll
    for (int ks = 0; ks < 4; ++ks) {
        const int ca = ac0 + 2 * ks;   // A chunk index for this k-step
        const int cb = bc0 + 2 * ks;   // B chunk index
        uint32_t bt[4][4];
#pragma unroll
        for (int nb = 0; nb < 4; ++nb)
            ldsm4(bt[nb], bB + bBase[nb] + (uint32_t)((cb ^ bx) << 4));  // n 16nb..16nb+15

        uint32_t a[4][4];
#pragma unroll
        for (int i = 0; i < 4; ++i)
            ldsm4(a[i], aB + aBase[i] + (uint32_t)((ca ^ ax[i]) << 4));

#pragma unroll
        for (int i = 0; i < 4; ++i) {
#pragma unroll
            for (int j = 0; j < 8; ++j) {
                mma_f16(c[i][j], a[i], bt[j >> 1][(j & 1) * 2], bt[j >> 1][(j & 1) * 2 + 1]);
            }
        }
    }
}

__global__ void __launch_bounds__(THREADS, 1)
gemm_kernel(const float* __restrict__ scale, const float* __restrict__ bias,
            float* __restrict__ out) {
    extern __shared__ char smem[];
    const uint32_t sb = smem_u32(smem);
    const int tid = threadIdx.x;
    const int wid = tid >> 5;        // 0..7
    const int l = tid & 31;

    const int nt = blockIdx.x;   // fastest -> W (90MB) stays L2-resident across mt sweep
    const int mt = blockIdx.y;
    const size_t mBase = (size_t)mt * BM;
    const size_t nBase = (size_t)nt * BN;

    const __half* Ax = g_xh + mBase * K_DIM;
    const __half* Bw = g_w + nBase * K_DIM;

    const int wm = (wid & 3) * 64;   // 4(m) x 2(n) warp grid, 64x64 warp tile
    const int wn = (wid >> 2) * 64;

    float c[4][8][4];                // 128 f32 accumulators
#pragma unroll
    for (int i = 0; i < 4; ++i)
#pragma unroll
        for (int j = 0; j < 8; ++j)
#pragma unroll
            for (int k = 0; k < 4; ++k) c[i][j][k] = 0.0f;

    // prologue: pair 0 (stages 0,1) into pair-buffer 0
    load_stage(sb + 0 * STAGE_BYTES, Ax, Bw, 0, tid);
    load_stage(sb + 1 * STAGE_BYTES, Ax, Bw, 1, tid);
    CP_COMMIT();

    // Pair-staged mainloop: one wait + one sync per TWO K-stages (32 total).
    // Ring of 2 pair-buffers; next pair's load overlaps current pair's compute.
    for (int p = 0; p < NPAIR; ++p) {
        CP_WAIT(0);                // pair p resident (and prior buffers reusable)
        __syncthreads();           // all warps done with pair p-1's buffers
        const uint32_t cur = sb + (uint32_t)(p & 1) * (2 * STAGE_BYTES);
        const uint32_t nxt = sb + (uint32_t)((p + 1) & 1) * (2 * STAGE_BYTES);
        if (p + 1 < NPAIR) {
            load_stage(nxt,               Ax, Bw, 2 * p + 2, tid);
            load_stage(nxt + STAGE_BYTES, Ax, Bw, 2 * p + 3, tid);
            CP_COMMIT();
        }
        tile_compute(cur,               l, wm, wn, c);
        tile_compute(cur + STAGE_BYTES, l, wm, wn, c);
    }

    // ---------------- epilogue: scale + bias + exact GELU ----------------
    const int gid = l >> 2, tig = l & 3;

    float wv[16], bv[16];
#pragma unroll
    for (int j = 0; j < 8; ++j) {
        const size_t n0 = nBase + wn + 8 * j + 2 * tig;
        wv[2 * j] = scale[n0]; wv[2 * j + 1] = scale[n0 + 1];
        bv[2 * j] = bias[n0];  bv[2 * j + 1] = bias[n0 + 1];
    }

#pragma unroll
    for (int i = 0; i < 4; ++i) {
#pragma unroll
        for (int j = 0; j < 8; ++j) {
            const size_t n0 = nBase + wn + 8 * j + 2 * tig;
#pragma unroll
            for (int h = 0; h < 2; ++h) {
                const size_t m = mBase + wm + 16 * i + gid + 8 * h;
                float y0 = fmaf(c[i][j][2 * h],     wv[2 * j],     bv[2 * j]);
                float y1 = fmaf(c[i][j][2 * h + 1], wv[2 * j + 1], bv[2 * j + 1]);
                float g0 = 0.5f * y0 * (1.0f + erff(y0 * 0.70710678118654752f));
                float g1 = 0.5f * y1 * (1.0f + erff(y1 * 0.70710678118654752f));
                float2 vv; vv.x = g0; vv.y = g1;
                __stcg(reinterpret_cast<float2*>(out + m * N_DIM + n0), vv);
            }
        }
    }
}

// ---------------- launch ----------------
extern "C" void kernel_launch(void* const* d_in, const int* in_sizes, int n_in,
                              void* d_out, int out_size) {
    const float* x     = (const float*)d_in[0];
    const int*   Wq    = (const int*)d_in[1];
    const float* scale = (const float*)d_in[2];
    const float* bias  = (const float*)d_in[3];
    float* out = (float*)d_out;
    (void)in_sizes; (void)n_in; (void)out_size;

    // x -> fp16
    {
        const int n4 = (M_DIM * K_DIM) / 4;   // 8388608
        cvt_x_kernel<<<(n4 + 255) / 256, 256>>>((const float4*)x, n4);
    }
    // Wq int32 -> fp16 (exact)
    {
        const int n4 = (N_DIM * K_DIM) / 4;   // 11272192
        cvt_w_kernel<<<(n4 + 255) / 256, 256>>>((const int4*)Wq, n4);
    }
    // GEMM + fused epilogue
    cudaFuncSetAttribute(gemm_kernel, cudaFuncAttributeMaxDynamicSharedMemorySize,
                         SMEM_BYTES);
    dim3 grid(N_DIM / BN, M_DIM / BM);        // (86, 32), nt fastest
    gemm_kernel<<<grid, THREADS, SMEM_BYTES>>>(scale, bias, out);
}